// round 1
// baseline (speedup 1.0000x reference)
#include <cuda_runtime.h>
#include <cuda_bf16.h>
#include <math.h>
#include <stdint.h>

// Problem shapes (fixed for this problem instance)
#define BB 64
#define TT 512
#define DD 1024
#define UU 128
#define MM (BB * TT)   // 32768 rows of logits

// Scratch: logits [B*T, U] fp32 = 16.8 MB (no cudaMalloc allowed)
__device__ float g_logits[MM * UU];

// ---------------------------------------------------------------------------
// Kernel 1: logits = X(M,K) @ W(K,U) + bias   (fp32 SIMT GEMM)
// Tile: BM=128, BN=128(=U), BK=16; 256 threads; 8x8 accum per thread.
// ---------------------------------------------------------------------------
#define GBM 128
#define GBK 16

__global__ __launch_bounds__(256, 2)
void gemm_bias_kernel(const float* __restrict__ A,
                      const float* __restrict__ W,
                      const float* __restrict__ bias)
{
    __shared__ float As[GBK][GBM];      // A tile, transposed: As[k][m]
    __shared__ float Bs[GBK][UU];       // W tile: Bs[k][n]

    const int tid  = threadIdx.x;
    const int row0 = blockIdx.x * GBM;

    // A-load mapping: 128 rows x 16 k = 2048 floats; each thread 2x float4
    const int arow = tid >> 2;          // 0..63
    const int ak   = (tid & 3) * 4;     // 0,4,8,12
    // W-load mapping: 16 k x 128 n = 2048 floats; each thread 2x float4
    const int wk   = tid >> 5;          // 0..7
    const int wcol = (tid & 31) * 4;    // 0..124

    const int tx = tid & 15;            // 0..15 -> n block of 8
    const int ty = tid >> 4;            // 0..15 -> m block of 8

    float acc[8][8];
    #pragma unroll
    for (int i = 0; i < 8; i++)
        #pragma unroll
        for (int j = 0; j < 8; j++)
            acc[i][j] = 0.0f;

    for (int k0 = 0; k0 < DD; k0 += GBK) {
        // Load A tile (transpose into As[k][m])
        #pragma unroll
        for (int i = 0; i < 2; i++) {
            const float4 v = *reinterpret_cast<const float4*>(
                &A[(size_t)(row0 + arow + i * 64) * DD + k0 + ak]);
            As[ak + 0][arow + i * 64] = v.x;
            As[ak + 1][arow + i * 64] = v.y;
            As[ak + 2][arow + i * 64] = v.z;
            As[ak + 3][arow + i * 64] = v.w;
        }
        // Load W tile
        #pragma unroll
        for (int i = 0; i < 2; i++) {
            const float4 v = *reinterpret_cast<const float4*>(
                &W[(size_t)(k0 + wk + i * 8) * UU + wcol]);
            *reinterpret_cast<float4*>(&Bs[wk + i * 8][wcol]) = v;
        }
        __syncthreads();

        #pragma unroll
        for (int k = 0; k < GBK; k++) {
            float a[8], b[8];
            *reinterpret_cast<float4*>(&a[0]) =
                *reinterpret_cast<const float4*>(&As[k][ty * 8]);
            *reinterpret_cast<float4*>(&a[4]) =
                *reinterpret_cast<const float4*>(&As[k][ty * 8 + 4]);
            *reinterpret_cast<float4*>(&b[0]) =
                *reinterpret_cast<const float4*>(&Bs[k][tx * 8]);
            *reinterpret_cast<float4*>(&b[4]) =
                *reinterpret_cast<const float4*>(&Bs[k][tx * 8 + 4]);
            #pragma unroll
            for (int i = 0; i < 8; i++)
                #pragma unroll
                for (int j = 0; j < 8; j++)
                    acc[i][j] = fmaf(a[i], b[j], acc[i][j]);
        }
        __syncthreads();
    }

    // Epilogue: add bias, write logits
    float bv[8];
    *reinterpret_cast<float4*>(&bv[0]) =
        *reinterpret_cast<const float4*>(&bias[tx * 8]);
    *reinterpret_cast<float4*>(&bv[4]) =
        *reinterpret_cast<const float4*>(&bias[tx * 8 + 4]);

    #pragma unroll
    for (int i = 0; i < 8; i++) {
        const size_t row = (size_t)(row0 + ty * 8 + i);
        float4 o0, o1;
        o0.x = acc[i][0] + bv[0]; o0.y = acc[i][1] + bv[1];
        o0.z = acc[i][2] + bv[2]; o0.w = acc[i][3] + bv[3];
        o1.x = acc[i][4] + bv[4]; o1.y = acc[i][5] + bv[5];
        o1.z = acc[i][6] + bv[6]; o1.w = acc[i][7] + bv[7];
        *reinterpret_cast<float4*>(&g_logits[row * UU + tx * 8])     = o0;
        *reinterpret_cast<float4*>(&g_logits[row * UU + tx * 8 + 4]) = o1;
    }
}

// ---------------------------------------------------------------------------
// Kernel 2: Viterbi forward + backtrace. One CTA per batch, 256 threads.
// Thread t: u = t>>1, half = t&1. Each thread scans 64 u' with the chain
// column in registers; thread pairs (lanes 2u, 2u+1) combine via shfl.xor 1.
// Backpointers (511 x 128 u8) kept in shared memory; backtrace is an LDS
// pointer chase by thread 0.
// ---------------------------------------------------------------------------
__global__ __launch_bounds__(256, 1)
void viterbi_kernel(const float* __restrict__ chain,
                    float* __restrict__ out)
{
    extern __shared__ char smem[];
    uint8_t* bp    = reinterpret_cast<uint8_t*>(smem);            // [511][128]
    float*   state = reinterpret_cast<float*>(smem + 511 * 128);  // [2][128]

    const int tid  = threadIdx.x;
    const int b    = blockIdx.x;
    const int u    = tid >> 1;        // 0..127
    const int half = tid & 1;         // 0 or 1  -> u' chunk [half*64, half*64+64)

    const float* lg = g_logits + (size_t)b * TT * UU;

    // Chain column for state u, our 64 u' rows, in registers
    float creg[64];
    #pragma unroll
    for (int j = 0; j < 64; j++)
        creg[j] = chain[(size_t)(half * 64 + j) * UU + u];

    // Initial state = logits[b][0][:]
    if (half == 0)
        state[u] = lg[u];
    __syncthreads();

    int cur = 0;
    // Prefetch pot for step 1
    float potbuf = lg[1 * UU + u];

    for (int t = 1; t < TT; t++) {
        const float pot = potbuf;
        if (t + 1 < TT)
            potbuf = lg[(size_t)(t + 1) * UU + u];

        const float* st = state + cur * UU;

        float best = -INFINITY;
        int   bi   = half * 64;
        #pragma unroll
        for (int j = 0; j < 64; j += 4) {
            const float4 s4 = *reinterpret_cast<const float4*>(&st[half * 64 + j]);
            float s;
            s = s4.x + creg[j + 0]; if (s > best) { best = s; bi = half * 64 + j + 0; }
            s = s4.y + creg[j + 1]; if (s > best) { best = s; bi = half * 64 + j + 1; }
            s = s4.z + creg[j + 2]; if (s > best) { best = s; bi = half * 64 + j + 2; }
            s = s4.w + creg[j + 3]; if (s > best) { best = s; bi = half * 64 + j + 3; }
        }

        // Combine thread pair (adjacent lanes)
        const float ov = __shfl_xor_sync(0xffffffffu, best, 1);
        const int   oi = __shfl_xor_sync(0xffffffffu, bi, 1);
        if (ov > best || (ov == best && oi < bi)) { best = ov; bi = oi; }

        if (half == 0) {
            state[(cur ^ 1) * UU + u] = pot + best;
            bp[(size_t)(t - 1) * UU + u] = (uint8_t)bi;
        }
        cur ^= 1;
        __syncthreads();
    }

    // Backtrace (thread 0): argmax of final state then LDS chase
    if (tid == 0) {
        const float* fs = state + cur * UU;
        float bv = fs[0];
        int tag = 0;
        for (int k = 1; k < UU; k++) {
            const float v = fs[k];
            if (v > bv) { bv = v; tag = k; }
        }
        float* o = out + (size_t)b * TT;
        o[TT - 1] = (float)tag;
        for (int t = TT - 2; t >= 0; t--) {
            tag = bp[(size_t)t * UU + tag];
            o[t] = (float)tag;
        }
    }
}

// ---------------------------------------------------------------------------
extern "C" void kernel_launch(void* const* d_in, const int* in_sizes, int n_in,
                              void* d_out, int out_size)
{
    const float* inputs = (const float*)d_in[0];   // (B,T,D)
    const float* kernel = (const float*)d_in[1];   // (D,U)
    const float* bias   = (const float*)d_in[2];   // (U)
    const float* chain  = (const float*)d_in[3];   // (U,U)
    float* out = (float*)d_out;                    // (B,T) as float

    (void)in_sizes; (void)n_in; (void)out_size;

    // GEMM: 32768/128 = 256 CTAs
    gemm_bias_kernel<<<MM / GBM, 256>>>(inputs, kernel, bias);

    // Viterbi: 64 CTAs (one per batch), dynamic smem = bp + 2 state buffers
    const int smem_bytes = 511 * 128 + 2 * UU * (int)sizeof(float); // 66432
    cudaFuncSetAttribute(viterbi_kernel,
                         cudaFuncAttributeMaxDynamicSharedMemorySize,
                         smem_bytes);
    viterbi_kernel<<<BB, 256, smem_bytes>>>(chain, out);
}

// round 2
// speedup vs baseline: 1.0269x; 1.0269x over previous
#include <cuda_runtime.h>
#include <cuda_bf16.h>
#include <math.h>
#include <stdint.h>

// Problem shapes (fixed)
#define BB 64
#define TT 512
#define DD 1024
#define UU 128
#define MM (BB * TT)

typedef unsigned long long u64;

// Scratch: logits, overwritten in-place by viterbi state values. 16.8 MB.
__device__ float g_logits[MM * UU];

// ---------------- packed fp32 helpers (Blackwell f32x2) ---------------------
#define FMA2(d, a, b, c) \
    asm("fma.rn.f32x2 %0, %1, %2, %3;" : "=l"(d) : "l"(a), "l"(b), "l"(c))
#define PACK2(d, lo, hi) \
    asm("mov.b64 %0, {%1, %2};" : "=l"(d) : "r"(__float_as_uint(lo)), "r"(__float_as_uint(hi)))
#define UNPK2(lo, hi, v) \
    asm("mov.b64 {%0, %1}, %2;" : "=r"(lo), "=r"(hi) : "l"(v))

// ---------------------------------------------------------------------------
// Kernel 1: logits = X(M,K) @ W(K,U) + bias, exact fp32 via fma.rn.f32x2.
// Tile BM=128, BN=128, BK=16; 256 threads; 8x8 accum per thread (as 8x4 pairs)
// ---------------------------------------------------------------------------
#define GBM 128
#define GBK 16

__global__ __launch_bounds__(256, 2)
void gemm_bias_kernel(const float* __restrict__ A,
                      const float* __restrict__ W,
                      const float* __restrict__ bias)
{
    __shared__ float As[GBK][GBM];
    __shared__ float Bs[GBK][UU];

    const int tid  = threadIdx.x;
    const int row0 = blockIdx.x * GBM;

    const int arow = tid >> 2;
    const int ak   = (tid & 3) * 4;
    const int wk   = tid >> 5;
    const int wcol = (tid & 31) * 4;

    const int tx = tid & 15;
    const int ty = tid >> 4;

    u64 acc2[8][4];
    #pragma unroll
    for (int i = 0; i < 8; i++)
        #pragma unroll
        for (int j = 0; j < 4; j++)
            acc2[i][j] = 0ull;

    for (int k0 = 0; k0 < DD; k0 += GBK) {
        #pragma unroll
        for (int i = 0; i < 2; i++) {
            const float4 v = *reinterpret_cast<const float4*>(
                &A[(size_t)(row0 + arow + i * 64) * DD + k0 + ak]);
            As[ak + 0][arow + i * 64] = v.x;
            As[ak + 1][arow + i * 64] = v.y;
            As[ak + 2][arow + i * 64] = v.z;
            As[ak + 3][arow + i * 64] = v.w;
        }
        #pragma unroll
        for (int i = 0; i < 2; i++) {
            const float4 v = *reinterpret_cast<const float4*>(
                &W[(size_t)(k0 + wk + i * 8) * UU + wcol]);
            *reinterpret_cast<float4*>(&Bs[wk + i * 8][wcol]) = v;
        }
        __syncthreads();

        #pragma unroll
        for (int k = 0; k < GBK; k++) {
            float a[8];
            *reinterpret_cast<float4*>(&a[0]) =
                *reinterpret_cast<const float4*>(&As[k][ty * 8]);
            *reinterpret_cast<float4*>(&a[4]) =
                *reinterpret_cast<const float4*>(&As[k][ty * 8 + 4]);
            // b pairs loaded directly as packed u64 (adjacent columns)
            const ulonglong2 b01 =
                *reinterpret_cast<const ulonglong2*>(&Bs[k][tx * 8]);
            const ulonglong2 b23 =
                *reinterpret_cast<const ulonglong2*>(&Bs[k][tx * 8 + 4]);
            u64 pb0 = b01.x, pb1 = b01.y, pb2 = b23.x, pb3 = b23.y;

            #pragma unroll
            for (int i = 0; i < 8; i++) {
                u64 ad;
                PACK2(ad, a[i], a[i]);
                FMA2(acc2[i][0], ad, pb0, acc2[i][0]);
                FMA2(acc2[i][1], ad, pb1, acc2[i][1]);
                FMA2(acc2[i][2], ad, pb2, acc2[i][2]);
                FMA2(acc2[i][3], ad, pb3, acc2[i][3]);
            }
        }
        __syncthreads();
    }

    // Epilogue: bias + store
    float bv[8];
    *reinterpret_cast<float4*>(&bv[0]) =
        *reinterpret_cast<const float4*>(&bias[tx * 8]);
    *reinterpret_cast<float4*>(&bv[4]) =
        *reinterpret_cast<const float4*>(&bias[tx * 8 + 4]);

    #pragma unroll
    for (int i = 0; i < 8; i++) {
        float c[8];
        #pragma unroll
        for (int j = 0; j < 4; j++) {
            unsigned lo, hi;
            UNPK2(lo, hi, acc2[i][j]);
            c[2 * j]     = __uint_as_float(lo);
            c[2 * j + 1] = __uint_as_float(hi);
        }
        const size_t row = (size_t)(row0 + ty * 8 + i);
        float4 o0, o1;
        o0.x = c[0] + bv[0]; o0.y = c[1] + bv[1];
        o0.z = c[2] + bv[2]; o0.w = c[3] + bv[3];
        o1.x = c[4] + bv[4]; o1.y = c[5] + bv[5];
        o1.z = c[6] + bv[6]; o1.w = c[7] + bv[7];
        *reinterpret_cast<float4*>(&g_logits[row * UU + tx * 8])     = o0;
        *reinterpret_cast<float4*>(&g_logits[row * UU + tx * 8 + 4]) = o1;
    }
}

// ---------------------------------------------------------------------------
// Kernel 2: Viterbi. One CTA/batch, 256 threads.
// Forward: max values only (FADD+FMNMX), state history written in-place over
// g_logits. Backtrace: warp 0 recomputes argmax per step from state history +
// transposed chain in smem, exact ordered-int keys + redux.sync.
// ---------------------------------------------------------------------------
__device__ __forceinline__ unsigned fkey(float f)
{
    const unsigned b = __float_as_uint(f);
    return b ^ ((unsigned)(((int)b) >> 31) | 0x80000000u);
}
__device__ __forceinline__ unsigned redux_max_u32(unsigned v)
{
    unsigned r;
    asm("redux.sync.max.u32 %0, %1, 0xffffffff;" : "=r"(r) : "r"(v));
    return r;
}
__device__ __forceinline__ unsigned redux_min_u32(unsigned v)
{
    unsigned r;
    asm("redux.sync.min.u32 %0, %1, 0xffffffff;" : "=r"(r) : "r"(v));
    return r;
}

__global__ __launch_bounds__(256, 1)
void viterbi_kernel(const float* __restrict__ chain,
                    float* __restrict__ out)
{
    extern __shared__ float sm[];
    float* chT   = sm;             // [128][128]: chT[u][u'] = chain[u'][u]
    float* state = sm + UU * UU;   // [2][128]

    const int tid  = threadIdx.x;
    const int b    = blockIdx.x;
    const int u    = tid >> 1;
    const int half = tid & 1;

    float* lg = g_logits + (size_t)b * TT * UU;   // logits, becomes state

    // Transpose chain into smem (for backtrace)
    for (int i = tid; i < UU * UU; i += 256) {
        const int r = i >> 7, c = i & 127;
        chT[c * UU + r] = chain[i];
    }

    // Chain column for state u, our 64 u' rows, in registers
    float creg[64];
    #pragma unroll
    for (int j = 0; j < 64; j++)
        creg[j] = chain[(size_t)(half * 64 + j) * UU + u];

    if (half == 0)
        state[u] = lg[u];
    __syncthreads();

    int cur = 0;
    float potbuf = lg[UU + u];

    for (int t = 1; t < TT; t++) {
        const float pot = potbuf;
        if (t + 1 < TT)
            potbuf = lg[(size_t)(t + 1) * UU + u];

        const float* st = state + cur * UU;

        float m0 = -INFINITY, m1 = -INFINITY, m2 = -INFINITY, m3 = -INFINITY;
        #pragma unroll
        for (int j = 0; j < 64; j += 4) {
            const float4 s4 = *reinterpret_cast<const float4*>(&st[half * 64 + j]);
            m0 = fmaxf(m0, s4.x + creg[j + 0]);
            m1 = fmaxf(m1, s4.y + creg[j + 1]);
            m2 = fmaxf(m2, s4.z + creg[j + 2]);
            m3 = fmaxf(m3, s4.w + creg[j + 3]);
        }
        float m = fmaxf(fmaxf(m0, m1), fmaxf(m2, m3));
        m = fmaxf(m, __shfl_xor_sync(0xffffffffu, m, 1));

        const float ns = pot + m;
        if (half == 0)
            state[(cur ^ 1) * UU + u] = ns;     // smem for next step
        else
            lg[(size_t)t * UU + u] = ns;        // global history for backtrace
        cur ^= 1;
        __syncthreads();
    }

    // ---------------- Backtrace: warp 0 only ----------------
    if (tid < 32) {
        const int lane = tid;
        float* o = out + (size_t)b * TT;

        // Final tag = argmax of state[511]
        const float4 fs =
            *reinterpret_cast<const float4*>(&state[cur * UU + lane * 4]);
        unsigned k0 = fkey(fs.x), k1 = fkey(fs.y);
        unsigned k2 = fkey(fs.z), k3 = fkey(fs.w);
        unsigned M = redux_max_u32(umax(umax(k0, k1), umax(k2, k3)));
        unsigned idx = 0x7fffffffu;
        if (k3 == M) idx = lane * 4 + 3;
        if (k2 == M) idx = lane * 4 + 2;
        if (k1 == M) idx = lane * 4 + 1;
        if (k0 == M) idx = lane * 4 + 0;
        unsigned tag = redux_min_u32(idx);
        if (lane == 0) o[TT - 1] = (float)tag;

        // Walk back: tag_t = argmax_{u'}( state[t][u'] + chain[u'][tag_{t+1}] )
        float4 sb = *reinterpret_cast<const float4*>(
            &lg[(size_t)(TT - 2) * UU + lane * 4]);
        for (int t = TT - 2; t >= 0; t--) {
            const float4 sv = sb;
            if (t > 0)
                sb = *reinterpret_cast<const float4*>(
                    &lg[(size_t)(t - 1) * UU + lane * 4]);
            const float4 ch =
                *reinterpret_cast<const float4*>(&chT[tag * UU + lane * 4]);
            k0 = fkey(sv.x + ch.x);
            k1 = fkey(sv.y + ch.y);
            k2 = fkey(sv.z + ch.z);
            k3 = fkey(sv.w + ch.w);
            M = redux_max_u32(umax(umax(k0, k1), umax(k2, k3)));
            idx = 0x7fffffffu;
            if (k3 == M) idx = lane * 4 + 3;
            if (k2 == M) idx = lane * 4 + 2;
            if (k1 == M) idx = lane * 4 + 1;
            if (k0 == M) idx = lane * 4 + 0;
            tag = redux_min_u32(idx);
            if (lane == 0) o[t] = (float)tag;
        }
    }
}

// ---------------------------------------------------------------------------
extern "C" void kernel_launch(void* const* d_in, const int* in_sizes, int n_in,
                              void* d_out, int out_size)
{
    const float* inputs = (const float*)d_in[0];   // (B,T,D)
    const float* kernel = (const float*)d_in[1];   // (D,U)
    const float* bias   = (const float*)d_in[2];   // (U)
    const float* chain  = (const float*)d_in[3];   // (U,U)
    float* out = (float*)d_out;                    // (B,T)

    (void)in_sizes; (void)n_in; (void)out_size;

    gemm_bias_kernel<<<MM / GBM, 256>>>(inputs, kernel, bias);

    const int smem_bytes = (UU * UU + 2 * UU) * (int)sizeof(float); // 66560
    cudaFuncSetAttribute(viterbi_kernel,
                         cudaFuncAttributeMaxDynamicSharedMemorySize,
                         smem_bytes);
    viterbi_kernel<<<BB, 256, smem_bytes>>>(chain, out);
}